// round 3
// baseline (speedup 1.0000x reference)
#include <cuda_runtime.h>
#include <math.h>

#define D_MODEL 1024
#define N_HEADS 16
#define HEAD_DIM 64
#define B_SIZE 4
#define T_LEN 2048
#define TOKENS (B_SIZE * T_LEN)   // 8192

// Scratch (device globals: allocation-free per harness rules)
__device__ float g_qkv[(size_t)TOKENS * 3 * D_MODEL];   // [B,T,3,H,Dh] = 96 MB
__device__ float g_attn[(size_t)TOKENS * D_MODEL];      // [B,T,C]     = 32 MB

// ---------------------------------------------------------------------------
// C[M,N] = A[M,K] @ W[N,K]^T + bias[N]     (both row-major, K contiguous)
// 128x128 block, BK=16, 256 threads, 8x8 micro-tile per thread.
// M,N multiples of 128; K multiple of 16 (true for all our shapes).
// ---------------------------------------------------------------------------
__global__ __launch_bounds__(256)
void gemm_nt_bias(const float* __restrict__ A, const float* __restrict__ W,
                  const float* __restrict__ bias, float* __restrict__ C,
                  int M, int N, int K)
{
    const int BM = 128, BN = 128, BK = 16;
    __shared__ float As[BK][BM + 4];
    __shared__ float Ws[BK][BN + 4];

    const int tid  = threadIdx.x;
    const int brow = blockIdx.y * BM;
    const int bcol = blockIdx.x * BN;
    const int ty   = tid >> 4;       // 0..15
    const int tx   = tid & 15;       // 0..15

    float acc[8][8];
    #pragma unroll
    for (int i = 0; i < 8; i++)
        #pragma unroll
        for (int j = 0; j < 8; j++) acc[i][j] = 0.f;

    for (int k0 = 0; k0 < K; k0 += BK) {
        // Load A tile (128x16) and W tile (128x16), transposed into smem.
        #pragma unroll
        for (int i = 0; i < 2; i++) {
            int idx = tid + i * 256;          // 0..511 float4 slots
            int row = idx >> 2;               // 0..127
            int kv  = (idx & 3) << 2;         // 0,4,8,12
            float4 av = *(const float4*)(A + (size_t)(brow + row) * K + k0 + kv);
            As[kv + 0][row] = av.x; As[kv + 1][row] = av.y;
            As[kv + 2][row] = av.z; As[kv + 3][row] = av.w;
            float4 wv = *(const float4*)(W + (size_t)(bcol + row) * K + k0 + kv);
            Ws[kv + 0][row] = wv.x; Ws[kv + 1][row] = wv.y;
            Ws[kv + 2][row] = wv.z; Ws[kv + 3][row] = wv.w;
        }
        __syncthreads();

        #pragma unroll
        for (int kk = 0; kk < BK; kk++) {
            float a[8], b[8];
            #pragma unroll
            for (int i = 0; i < 8; i++) a[i] = As[kk][ty * 8 + i];
            #pragma unroll
            for (int j = 0; j < 8; j++) b[j] = Ws[kk][tx * 8 + j];
            #pragma unroll
            for (int i = 0; i < 8; i++)
                #pragma unroll
                for (int j = 0; j < 8; j++)
                    acc[i][j] = fmaf(a[i], b[j], acc[i][j]);
        }
        __syncthreads();
    }

    #pragma unroll
    for (int i = 0; i < 8; i++) {
        int row = brow + ty * 8 + i;
        #pragma unroll
        for (int j = 0; j < 8; j++) {
            int col = bcol + tx * 8 + j;
            C[(size_t)row * N + col] = acc[i][j] + bias[col];
        }
    }
}

// ---------------------------------------------------------------------------
// Causal flash attention, fp32.
// qkv layout per token: [3, H, 64] (stride 3072 floats per token).
// Grid: (T/TQ, H, B). Block: TQ threads; each thread owns one query row.
// Online softmax over key tiles of TK rows held in smem; causal tile skip.
// ---------------------------------------------------------------------------
#define TQ 128
#define TK 16

__global__ __launch_bounds__(128)
void flash_attn(const float* __restrict__ qkv, float* __restrict__ out)
{
    const int b   = blockIdx.z;
    const int h   = blockIdx.y;
    const int q0  = blockIdx.x * TQ;
    const int tid = threadIdx.x;
    const int q   = q0 + tid;
    const size_t tok = 3 * D_MODEL;   // 3072 floats per token

    const float* qp = qkv + (size_t)(b * T_LEN + q) * tok + h * HEAD_DIM;
    float qr[64];
    #pragma unroll
    for (int d = 0; d < 64; d++) qr[d] = qp[d] * 0.125f;   // fold 1/sqrt(64)

    float o[64];
    #pragma unroll
    for (int d = 0; d < 64; d++) o[d] = 0.f;
    float m = -INFINITY, l = 0.f;

    __shared__ float Ks[TK][64];
    __shared__ float Vs[TK][64];

    const float* kb = qkv + (size_t)b * T_LEN * tok + 1 * D_MODEL + h * HEAD_DIM;
    const float* vb = qkv + (size_t)b * T_LEN * tok + 2 * D_MODEL + h * HEAD_DIM;

    for (int k0 = 0; k0 < q0 + TQ; k0 += TK) {   // causal: skip tiles beyond block diag
        // Load K/V tiles: 16 rows x 64 floats = 256 float4 per tile, 2 per thread.
        #pragma unroll
        for (int i = 0; i < 2; i++) {
            int idx = tid + i * 128;
            int row = idx >> 4;
            int cv  = (idx & 15) << 2;
            *(float4*)&Ks[row][cv] = *(const float4*)(kb + (size_t)(k0 + row) * tok + cv);
            *(float4*)&Vs[row][cv] = *(const float4*)(vb + (size_t)(k0 + row) * tok + cv);
        }
        __syncthreads();

        float s[TK];
        #pragma unroll
        for (int j = 0; j < TK; j++) {
            float acc = 0.f;
            #pragma unroll
            for (int d = 0; d < 64; d++) acc = fmaf(qr[d], Ks[j][d], acc);
            s[j] = (k0 + j <= q) ? acc : -INFINITY;
        }

        float mt = m;
        #pragma unroll
        for (int j = 0; j < TK; j++) mt = fmaxf(mt, s[j]);
        // First tile always contains key 0 (<= q), so mt is finite once used.
        float corr = __expf(m - mt);
        l *= corr;
        #pragma unroll
        for (int d = 0; d < 64; d++) o[d] *= corr;
        #pragma unroll
        for (int j = 0; j < TK; j++) {
            float p = __expf(s[j] - mt);
            l += p;
            #pragma unroll
            for (int d = 0; d < 64; d++) o[d] = fmaf(p, Vs[j][d], o[d]);
        }
        m = mt;
        __syncthreads();
    }

    const float inv = 1.f / l;
    float* op = out + (size_t)(b * T_LEN + q) * D_MODEL + h * HEAD_DIM;
    #pragma unroll
    for (int d = 0; d < 64; d++) op[d] = o[d] * inv;
}

// ---------------------------------------------------------------------------
extern "C" void kernel_launch(void* const* d_in, const int* in_sizes, int n_in,
                              void* d_out, int out_size)
{
    // Identify inputs by element count (all five are distinct sizes):
    // x: 8388608, w_qkv: 3145728, b_qkv: 3072, w_out: 1048576, b_out: 1024
    const float *x = nullptr, *w_qkv = nullptr, *b_qkv = nullptr,
                *w_out = nullptr, *b_out = nullptr;
    for (int i = 0; i < n_in; i++) {
        switch (in_sizes[i]) {
            case 8388608: x     = (const float*)d_in[i]; break;
            case 3145728: w_qkv = (const float*)d_in[i]; break;
            case 3072:    b_qkv = (const float*)d_in[i]; break;
            case 1048576: w_out = (const float*)d_in[i]; break;
            case 1024:    b_out = (const float*)d_in[i]; break;
            default: break;
        }
    }
    float* out = (float*)d_out;

    float *qkv_buf = nullptr, *attn_buf = nullptr;
    cudaGetSymbolAddress((void**)&qkv_buf, g_qkv);
    cudaGetSymbolAddress((void**)&attn_buf, g_attn);

    // 1) QKV projection: [8192,1024] @ [3072,1024]^T + b -> [8192,3072]
    gemm_nt_bias<<<dim3(3 * D_MODEL / 128, TOKENS / 128), 256>>>(
        x, w_qkv, b_qkv, qkv_buf, TOKENS, 3 * D_MODEL, D_MODEL);

    // 2) Causal flash attention -> [B,T,C] (heads re-interleaved into C)
    flash_attn<<<dim3(T_LEN / TQ, N_HEADS, B_SIZE), TQ>>>(qkv_buf, attn_buf);

    // 3) Output projection: [8192,1024] @ [1024,1024]^T + b -> d_out
    gemm_nt_bias<<<dim3(D_MODEL / 128, TOKENS / 128), 256>>>(
        attn_buf, w_out, b_out, out, TOKENS, D_MODEL, D_MODEL);
}